// round 3
// baseline (speedup 1.0000x reference)
#include <cuda_runtime.h>
#include <cuda_bf16.h>
#include <stdint.h>

#define B_DIM 64
#define C_DIM 128
#define HW_DIM 16384
#define L_DIM 50
#define TILES_PER_CTA 8
#define TILE_PX 128

// shared memory map (units = 4 bytes)
#define STAG_STRIDE 132                 // fp32 staging row stride (floats)
#define XIMG_OFF32  16896               // bf16 x image [px][c], stride 68 u32
#define XIMG_STRIDE 68
#define KFRAG_OFF32 (XIMG_OFF32 + 68*128)   // 25600
#define VH_OFF32    (KFRAG_OFF32 + 4096)    // 29696
#define VL_OFF32    (VH_OFF32 + 4096)       // 33792
#define SSQ_OFF32   (VL_OFF32 + 4096)       // 37888
#define SMEM_U32    (SSQ_OFF32 + 128)       // 38016
#define SMEM_BYTES  (SMEM_U32 * 4)          // 152064

static __device__ __align__(16) uint32_t g_kfrag[4096];
static __device__ __align__(16) uint32_t g_vhfrag[4096];
static __device__ __align__(16) uint32_t g_vlfrag[4096];

// ---------------------------------------------------------------- helpers
__device__ __forceinline__ uint32_t packbf(float lo, float hi) {
    __nv_bfloat162 t = __floats2bfloat162_rn(lo, hi);
    return *(uint32_t*)&t;
}
__device__ __forceinline__ void split2(float a, float b, uint32_t& hi, uint32_t& lo) {
    __nv_bfloat16 ha = __float2bfloat16(a);
    __nv_bfloat16 hb = __float2bfloat16(b);
    hi = ((uint32_t)__bfloat16_as_ushort(hb) << 16) | (uint32_t)__bfloat16_as_ushort(ha);
    lo = packbf(a - __bfloat162float(ha), b - __bfloat162float(hb));
}
__device__ __forceinline__ void mma_bf16(float* d, const uint32_t* a,
                                         const uint32_t* b, const float* c) {
    asm volatile(
        "mma.sync.aligned.m16n8k16.row.col.f32.bf16.bf16.f32 "
        "{%0,%1,%2,%3}, {%4,%5,%6,%7}, {%8,%9}, {%10,%11,%12,%13};"
        : "=f"(d[0]), "=f"(d[1]), "=f"(d[2]), "=f"(d[3])
        : "r"(a[0]), "r"(a[1]), "r"(a[2]), "r"(a[3]),
          "r"(b[0]), "r"(b[1]),
          "f"(c[0]), "f"(c[1]), "f"(c[2]), "f"(c[3]));
}

// ---------------------------------------------------------------- prep
// Bake B fragments in exact mma.m16n8k16 lane order:
//   kfrag  : GEMM1 B[k=c][n=slot] = knorm[slot][c], 8 k-steps x 8 n-tiles
//   vh/vl  : GEMM2 B[k=slot][n=c] = values[slot][c] hi/lo, 4 k-steps x 16 n-tiles
// frag linear index = (((ks*NT + nt)*2 + r)*32 + lane)
__global__ void prep_kernel(const float* __restrict__ keys,
                            const float* __restrict__ values) {
    __shared__ float knorm[64];
    int tid = threadIdx.x;
    if (tid < 64) {
        float s = 0.f;
        if (tid < L_DIM) {
            for (int c = 0; c < C_DIM; c++) {
                float v = keys[tid * C_DIM + c];
                s += v * v;
            }
        }
        knorm[tid] = (tid < L_DIM) ? rsqrtf(fmaxf(s, 1e-24f)) : 0.f;
    }
    __syncthreads();

    for (int idx = tid; idx < 4096; idx += blockDim.x) {
        int lane = idx & 31, f = idx >> 5;
        int r = f & 1, f2 = f >> 1;
        int nt = f2 & 7, ks = f2 >> 3;
        int g = lane >> 2, q = lane & 3;
        int l = nt * 8 + g;
        int k0 = ks * 16 + 2 * q + 8 * r;
        float v0 = 0.f, v1 = 0.f;
        if (l < L_DIM) {
            v0 = keys[l * C_DIM + k0]     * knorm[l];
            v1 = keys[l * C_DIM + k0 + 1] * knorm[l];
        }
        g_kfrag[idx] = packbf(v0, v1);
    }
    for (int idx = tid; idx < 4096; idx += blockDim.x) {
        int lane = idx & 31, f = idx >> 5;
        int r = f & 1, f2 = f >> 1;
        int nt = f2 & 15, ks = f2 >> 4;
        int g = lane >> 2, q = lane & 3;
        int n = nt * 8 + g;               // channel
        int k0 = ks * 16 + 2 * q + 8 * r; // slot
        float v0 = (k0     < L_DIM) ? values[k0 * C_DIM + n]       : 0.f;
        float v1 = (k0 + 1 < L_DIM) ? values[(k0 + 1) * C_DIM + n] : 0.f;
        uint32_t hi, lo;
        split2(v0, v1, hi, lo);
        g_vhfrag[idx] = hi;
        g_vlfrag[idx] = lo;
    }
}

// ---------------------------------------------------------------- main
__global__ void __launch_bounds__(256, 1)
memmod_kernel(const float* __restrict__ x, float* __restrict__ out) {
    extern __shared__ float smem[];
    uint32_t* sm32 = (uint32_t*)smem;

    const int tid  = threadIdx.x;
    const int wid  = tid >> 5;
    const int lane = tid & 31;
    const int g    = lane >> 2;
    const int q    = lane & 3;
    const int b    = blockIdx.y;

    // copy baked fragment images into smem (48 KB, once per CTA)
    {
        const uint4* s1 = (const uint4*)g_kfrag;
        const uint4* s2 = (const uint4*)g_vhfrag;
        const uint4* s3 = (const uint4*)g_vlfrag;
        uint4* d1 = (uint4*)(sm32 + KFRAG_OFF32);
        uint4* d2 = (uint4*)(sm32 + VH_OFF32);
        uint4* d3 = (uint4*)(sm32 + VL_OFF32);
        #pragma unroll 4
        for (int i = tid; i < 1024; i += 256) {
            d1[i] = s1[i]; d2[i] = s2[i]; d3[i] = s3[i];
        }
    }
    __syncthreads();

    const float* xb = x   + (size_t)b * C_DIM * HW_DIM;
    float*       ob = out + (size_t)b * C_DIM * HW_DIM;

    const int m0   = wid * 16;
    const int row0 = m0 + g;
    const int row1 = m0 + g + 8;
    const int sw0  = ((row0 >> 3) & 3) << 3;
    const int sw1  = ((row1 >> 3) & 3) << 3;

    for (int t = 0; t < TILES_PER_CTA; t++) {
        const int n0 = (blockIdx.x * TILES_PER_CTA + t) * TILE_PX;

        // ---- phase 1: gmem -> fp32 staging [c][px], coalesced float4 ----
        #pragma unroll
        for (int i = 0; i < 16; i++) {
            int idx = tid + i * 256;
            int c   = idx >> 5;
            int j4  = (idx & 31) << 2;
            float4 v = *(const float4*)(xb + (size_t)c * HW_DIM + n0 + j4);
            *(float4*)(smem + c * STAG_STRIDE + j4) = v;
        }
        __syncthreads();

        // ---- phase 2: per-pixel ssq + bf16 x image [px][c] (XOR swizzled) ----
        if (tid < 128) {
            const int p  = tid;
            const int sw = ((p >> 3) & 3) << 3;
            float ssq = 0.f;
            #pragma unroll
            for (int cc = 0; cc < 64; cc++) {
                float v0 = smem[(2 * cc)     * STAG_STRIDE + p];
                float v1 = smem[(2 * cc + 1) * STAG_STRIDE + p];
                ssq += v0 * v0 + v1 * v1;
                sm32[XIMG_OFF32 + p * XIMG_STRIDE + (cc ^ sw)] = packbf(v0, v1);
            }
            smem[SSQ_OFF32 + p] = ssq;
        }
        __syncthreads();

        // ---- GEMM1: logits[16px x 64slots] per warp, 1-pass bf16 ----
        float acc1[8][4];
        #pragma unroll
        for (int nt = 0; nt < 8; nt++)
            #pragma unroll
            for (int i = 0; i < 4; i++) acc1[nt][i] = 0.f;

        const uint32_t* xim = sm32 + XIMG_OFF32;
        #pragma unroll
        for (int ks = 0; ks < 8; ks++) {
            uint32_t a[4];
            int c0 = 8 * ks + q;
            int c1 = c0 + 4;
            a[0] = xim[row0 * XIMG_STRIDE + (c0 ^ sw0)];
            a[1] = xim[row1 * XIMG_STRIDE + (c0 ^ sw1)];
            a[2] = xim[row0 * XIMG_STRIDE + (c1 ^ sw0)];
            a[3] = xim[row1 * XIMG_STRIDE + (c1 ^ sw1)];
            #pragma unroll
            for (int nt = 0; nt < 8; nt++) {
                const uint32_t* fptr = sm32 + KFRAG_OFF32 + ((ks * 8 + nt) * 2) * 32 + lane;
                uint32_t bb[2] = { fptr[0], fptr[32] };
                mma_bf16(acc1[nt], a, bb, acc1[nt]);
            }
        }

        // ---- softmax over 64 slots (quad-distributed), fp32 ----
        float rn0 = rsqrtf(fmaxf(smem[SSQ_OFF32 + row0], 1e-24f));
        float rn1 = rsqrtf(fmaxf(smem[SSQ_OFF32 + row1], 1e-24f));
        float mx0 = -1e30f, mx1 = -1e30f;
        #pragma unroll
        for (int nt = 0; nt < 8; nt++) {
            int l0 = nt * 8 + 2 * q, l1 = l0 + 1;
            acc1[nt][0] = (l0 < L_DIM) ? acc1[nt][0] * rn0 : -1e30f;
            acc1[nt][1] = (l1 < L_DIM) ? acc1[nt][1] * rn0 : -1e30f;
            acc1[nt][2] = (l0 < L_DIM) ? acc1[nt][2] * rn1 : -1e30f;
            acc1[nt][3] = (l1 < L_DIM) ? acc1[nt][3] * rn1 : -1e30f;
            mx0 = fmaxf(mx0, fmaxf(acc1[nt][0], acc1[nt][1]));
            mx1 = fmaxf(mx1, fmaxf(acc1[nt][2], acc1[nt][3]));
        }
        mx0 = fmaxf(mx0, __shfl_xor_sync(0xffffffffu, mx0, 1));
        mx0 = fmaxf(mx0, __shfl_xor_sync(0xffffffffu, mx0, 2));
        mx1 = fmaxf(mx1, __shfl_xor_sync(0xffffffffu, mx1, 1));
        mx1 = fmaxf(mx1, __shfl_xor_sync(0xffffffffu, mx1, 2));
        float s0 = 0.f, s1 = 0.f;
        #pragma unroll
        for (int nt = 0; nt < 8; nt++) {
            acc1[nt][0] = __expf(acc1[nt][0] - mx0);
            acc1[nt][1] = __expf(acc1[nt][1] - mx0);
            acc1[nt][2] = __expf(acc1[nt][2] - mx1);
            acc1[nt][3] = __expf(acc1[nt][3] - mx1);
            s0 += acc1[nt][0] + acc1[nt][1];
            s1 += acc1[nt][2] + acc1[nt][3];
        }
        s0 += __shfl_xor_sync(0xffffffffu, s0, 1);
        s0 += __shfl_xor_sync(0xffffffffu, s0, 2);
        s1 += __shfl_xor_sync(0xffffffffu, s1, 1);
        s1 += __shfl_xor_sync(0xffffffffu, s1, 2);
        float inv0 = 1.f / s0, inv1 = 1.f / s1;

        // weights -> GEMM2 A-frags (hi/lo), direct D->A layout mapping
        uint32_t wh[4][4], wl[4][4];
        #pragma unroll
        for (int ks = 0; ks < 4; ks++) {
            int ntA = 2 * ks, ntB = 2 * ks + 1;
            split2(acc1[ntA][0] * inv0, acc1[ntA][1] * inv0, wh[ks][0], wl[ks][0]);
            split2(acc1[ntA][2] * inv1, acc1[ntA][3] * inv1, wh[ks][1], wl[ks][1]);
            split2(acc1[ntB][0] * inv0, acc1[ntB][1] * inv0, wh[ks][2], wl[ks][2]);
            split2(acc1[ntB][2] * inv1, acc1[ntB][3] * inv1, wh[ks][3], wl[ks][3]);
        }

        // ---- GEMM2: out[16px x 128ch] = W[16x64] * V[64x128], 3-pass ----
        float acc2[16][4];
        #pragma unroll
        for (int nt = 0; nt < 16; nt++)
            #pragma unroll
            for (int i = 0; i < 4; i++) acc2[nt][i] = 0.f;

        #pragma unroll
        for (int nt = 0; nt < 16; nt++) {
            #pragma unroll
            for (int ks = 0; ks < 4; ks++) {
                int fb = ((ks * 16 + nt) * 2) * 32 + lane;
                uint32_t bh[2] = { sm32[VH_OFF32 + fb], sm32[VH_OFF32 + fb + 32] };
                mma_bf16(acc2[nt], wh[ks], bh, acc2[nt]);
                mma_bf16(acc2[nt], wl[ks], bh, acc2[nt]);
                uint32_t bl[2] = { sm32[VL_OFF32 + fb], sm32[VL_OFF32 + fb + 32] };
                mma_bf16(acc2[nt], wh[ks], bl, acc2[nt]);
            }
        }

        // ---- epilogue: D2 frags -> gmem [c][px] (full 32B sectors) ----
        #pragma unroll
        for (int nt = 0; nt < 16; nt++) {
            int c0 = nt * 8 + 2 * q;
            size_t base = (size_t)c0 * HW_DIM + n0;
            ob[base + row0]          = acc2[nt][0];
            ob[base + HW_DIM + row0] = acc2[nt][1];
            ob[base + row1]          = acc2[nt][2];
            ob[base + HW_DIM + row1] = acc2[nt][3];
        }
        // loop-top __syncthreads (after phase 1) provides the needed barrier
    }
}

// ---------------------------------------------------------------- launcher
extern "C" void kernel_launch(void* const* d_in, const int* in_sizes, int n_in,
                              void* d_out, int out_size) {
    const float* x      = (const float*)d_in[0];
    const float* keys   = (const float*)d_in[1];
    const float* values = (const float*)d_in[2];
    float* out = (float*)d_out;

    cudaFuncSetAttribute(memmod_kernel,
                         cudaFuncAttributeMaxDynamicSharedMemorySize, SMEM_BYTES);

    prep_kernel<<<1, 256>>>(keys, values);
    dim3 grid(HW_DIM / (TILES_PER_CTA * TILE_PX), B_DIM);
    memmod_kernel<<<grid, 256, SMEM_BYTES>>>(x, out);
}

// round 4
// speedup vs baseline: 1.2440x; 1.2440x over previous
#include <cuda_runtime.h>
#include <cuda_bf16.h>
#include <stdint.h>

#define B_DIM 64
#define C_DIM 128
#define HW_DIM 16384
#define L_DIM 50
#define TILES_PER_CTA 8
#define TILE_PX 128
#define CHUNK_CH 32          // channels per staging chunk
#define N_CHUNKS 4

// shared memory map (u32 units)
#define STAG_OFF32  0                    // fp32 staging 32ch x 128px = 4096
#define XIMG_OFF32  4096                 // bf16x2 image [px][colmap], stride 65
#define XIMG_STRIDE 65                   // 65*128 = 8320
#define KF2_OFF32   12416                // uint2 kfrags: 2048 uint2 = 4096 u32
#define VF4_OFF32   16512                // uint4 vfrags: 2048 uint4 = 8192 u32
#define SSQ_OFF32   24704                // 256 floats
#define SMEM_U32    24960
#define SMEM_BYTES  (SMEM_U32 * 4)       // 99840

static __device__ __align__(16) uint2 g_kfrag2[2048];
static __device__ __align__(16) uint4 g_vfrag4[2048];

// ---------------------------------------------------------------- helpers
__device__ __forceinline__ uint32_t smem_u32(const void* p) {
    uint32_t a;
    asm("{ .reg .u64 t; cvta.to.shared.u64 t, %1; cvt.u32.u64 %0, t; }"
        : "=r"(a) : "l"(p));
    return a;
}
__device__ __forceinline__ void cp_async16(uint32_t dst, const void* src) {
    asm volatile("cp.async.cg.shared.global [%0], [%1], 16;"
                 :: "r"(dst), "l"(src));
}
__device__ __forceinline__ void cp_async_commit() {
    asm volatile("cp.async.commit_group;");
}
__device__ __forceinline__ void cp_async_wait0() {
    asm volatile("cp.async.wait_group 0;");
}
__device__ __forceinline__ uint32_t packbf(float lo, float hi) {
    __nv_bfloat162 t = __floats2bfloat162_rn(lo, hi);
    return *(uint32_t*)&t;
}
__device__ __forceinline__ void split2(float a, float b, uint32_t& hi, uint32_t& lo) {
    __nv_bfloat16 ha = __float2bfloat16(a);
    __nv_bfloat16 hb = __float2bfloat16(b);
    hi = ((uint32_t)__bfloat16_as_ushort(hb) << 16) | (uint32_t)__bfloat16_as_ushort(ha);
    lo = packbf(a - __bfloat162float(ha), b - __bfloat162float(hb));
}
__device__ __forceinline__ void mma_bf16(float* d, const uint32_t* a,
                                         const uint32_t* b, const float* c) {
    asm volatile(
        "mma.sync.aligned.m16n8k16.row.col.f32.bf16.bf16.f32 "
        "{%0,%1,%2,%3}, {%4,%5,%6,%7}, {%8,%9}, {%10,%11,%12,%13};"
        : "=f"(d[0]), "=f"(d[1]), "=f"(d[2]), "=f"(d[3])
        : "r"(a[0]), "r"(a[1]), "r"(a[2]), "r"(a[3]),
          "r"(b[0]), "r"(b[1]),
          "f"(c[0]), "f"(c[1]), "f"(c[2]), "f"(c[3]));
}

// ---------------------------------------------------------------- prep
// Same fragment values as the passing round-3 kernel, repacked:
//   kf2[(ks*8+nt)*32+lane]  = uint2{ b(r=0), b(r=1) }          (GEMM1 B, bf16)
//   vf4[(ks*16+nt)*32+lane] = uint4{ vh(r0), vh(r1), vl(r0), vl(r1) } (GEMM2 B)
__global__ void prep_kernel(const float* __restrict__ keys,
                            const float* __restrict__ values) {
    __shared__ float knorm[64];
    int tid = threadIdx.x;
    if (tid < 64) {
        float s = 0.f;
        if (tid < L_DIM) {
            for (int c = 0; c < C_DIM; c++) {
                float v = keys[tid * C_DIM + c];
                s += v * v;
            }
        }
        knorm[tid] = (tid < L_DIM) ? rsqrtf(fmaxf(s, 1e-24f)) : 0.f;
    }
    __syncthreads();

    for (int idx = tid; idx < 2048; idx += blockDim.x) {
        int lane = idx & 31, f = idx >> 5;
        int nt = f & 7, ks = f >> 3;
        int g = lane >> 2, q = lane & 3;
        int l = nt * 8 + g;
        uint2 o = make_uint2(0u, 0u);
        if (l < L_DIM) {
            float nrm = knorm[l];
            int k0 = ks * 16 + 2 * q;
            o.x = packbf(keys[l * C_DIM + k0]     * nrm,
                         keys[l * C_DIM + k0 + 1] * nrm);
            o.y = packbf(keys[l * C_DIM + k0 + 8]     * nrm,
                         keys[l * C_DIM + k0 + 8 + 1] * nrm);
        }
        g_kfrag2[idx] = o;
    }
    for (int idx = tid; idx < 2048; idx += blockDim.x) {
        int lane = idx & 31, f = idx >> 5;
        int nt = f & 15, ks = f >> 4;
        int g = lane >> 2, q = lane & 3;
        int n = nt * 8 + g;                 // channel
        int k0 = ks * 16 + 2 * q;           // slot (r=0)
        int k1 = k0 + 8;                    // slot (r=1)
        float a0 = (k0     < L_DIM) ? values[k0 * C_DIM + n]       : 0.f;
        float a1 = (k0 + 1 < L_DIM) ? values[(k0 + 1) * C_DIM + n] : 0.f;
        float b0 = (k1     < L_DIM) ? values[k1 * C_DIM + n]       : 0.f;
        float b1 = (k1 + 1 < L_DIM) ? values[(k1 + 1) * C_DIM + n] : 0.f;
        uint4 o;
        split2(a0, a1, o.x, o.z);
        split2(b0, b1, o.y, o.w);
        g_vfrag4[idx] = o;
    }
}

// ---------------------------------------------------------------- main
__global__ void __launch_bounds__(256, 2)
memmod_kernel(const float* __restrict__ x, float* __restrict__ out) {
    extern __shared__ float smem[];
    uint32_t* sm32 = (uint32_t*)smem;
    const uint32_t sbase = smem_u32(smem);

    const int tid  = threadIdx.x;
    const int wid  = tid >> 5;
    const int lane = tid & 31;
    const int g    = lane >> 2;
    const int q    = lane & 3;
    const int b    = blockIdx.y;

    // copy baked fragment images into smem (48 KB)
    {
        const uint4* s1 = (const uint4*)g_kfrag2;   // 1024 uint4
        const uint4* s2 = (const uint4*)g_vfrag4;   // 2048 uint4
        uint4* d1 = (uint4*)(sm32 + KF2_OFF32);
        uint4* d2 = (uint4*)(sm32 + VF4_OFF32);
        #pragma unroll
        for (int i = 0; i < 4; i++) d1[tid + i * 256] = s1[tid + i * 256];
        #pragma unroll
        for (int i = 0; i < 8; i++) d2[tid + i * 256] = s2[tid + i * 256];
    }

    const float* xb = x   + (size_t)b * C_DIM * HW_DIM;
    float*       ob = out + (size_t)b * C_DIM * HW_DIM;

    const int m0   = wid * 16;
    const int row0 = m0 + g;
    const int row1 = m0 + g + 8;
    const int p    = tid & 127;          // pixel for convert phase
    const int hh   = tid >> 7;           // channel-half for convert phase

    const uint2* kf2 = (const uint2*)(sm32 + KF2_OFF32);
    const uint4* vf4 = (const uint4*)(sm32 + VF4_OFF32);
    const uint32_t* xim = sm32 + XIMG_OFF32;

    for (int t = 0; t < TILES_PER_CTA; t++) {
        const int n0 = (blockIdx.x * TILES_PER_CTA + t) * TILE_PX;

        // ---- staged load + convert, 4 chunks of 32 channels ----
        float ssq = 0.f;
        for (int ch = 0; ch < N_CHUNKS; ch++) {
            __syncthreads();   // staging free (prev chunk consumed / prev tile done)
            const int c_local = tid >> 5;          // 0..7 step per i
            const int j4 = (tid & 31) << 2;
            #pragma unroll
            for (int i = 0; i < 4; i++) {
                int c = c_local + i * 8;
                cp_async16(sbase + (uint32_t)(c * 128 + j4) * 4,
                           xb + (size_t)(ch * CHUNK_CH + c) * HW_DIM + n0 + j4);
            }
            cp_async_commit();
            cp_async_wait0();
            __syncthreads();   // chunk visible to all

            // convert: thread (p, hh) handles 8 channel-pairs
            #pragma unroll
            for (int j = 0; j < 8; j++) {
                int ccl = hh * 8 + j;                    // local pair 0..15
                int cc  = ch * 16 + ccl;                 // global pair 0..63
                float v0 = smem[(2 * ccl)     * 128 + p];
                float v1 = smem[(2 * ccl + 1) * 128 + p];
                ssq += v0 * v0 + v1 * v1;
                int colmap = ((cc & 7) << 3) | (cc >> 3);
                sm32[XIMG_OFF32 + p * XIMG_STRIDE + colmap] = packbf(v0, v1);
            }
        }
        smem[SSQ_OFF32 + tid] = ssq;
        __syncthreads();

        // ---- GEMM1: logits[16px x 64slots] per warp, 1-pass bf16 ----
        float acc1[8][4];
        #pragma unroll
        for (int nt = 0; nt < 8; nt++)
            #pragma unroll
            for (int i = 0; i < 4; i++) acc1[nt][i] = 0.f;

        #pragma unroll
        for (int ks = 0; ks < 8; ks++) {
            uint32_t a[4];
            int base0 = row0 * XIMG_STRIDE + 8 * q + ks;
            int base1 = row1 * XIMG_STRIDE + 8 * q + ks;
            a[0] = xim[base0];
            a[1] = xim[base1];
            a[2] = xim[base0 + 32];
            a[3] = xim[base1 + 32];
            #pragma unroll
            for (int nt = 0; nt < 8; nt++) {
                uint2 bb = kf2[(ks * 8 + nt) * 32 + lane];
                mma_bf16(acc1[nt], a, (const uint32_t*)&bb, acc1[nt]);
            }
        }

        // ---- softmax over 64 slots (quad-distributed), fp32 ----
        float rn0 = rsqrtf(fmaxf(smem[SSQ_OFF32 + row0] +
                                 smem[SSQ_OFF32 + row0 + 128], 1e-24f));
        float rn1 = rsqrtf(fmaxf(smem[SSQ_OFF32 + row1] +
                                 smem[SSQ_OFF32 + row1 + 128], 1e-24f));
        float mx0 = -1e30f, mx1 = -1e30f;
        #pragma unroll
        for (int nt = 0; nt < 8; nt++) {
            int l0 = nt * 8 + 2 * q, l1 = l0 + 1;
            acc1[nt][0] = (l0 < L_DIM) ? acc1[nt][0] * rn0 : -1e30f;
            acc1[nt][1] = (l1 < L_DIM) ? acc1[nt][1] * rn0 : -1e30f;
            acc1[nt][2] = (l0 < L_DIM) ? acc1[nt][2] * rn1 : -1e30f;
            acc1[nt][3] = (l1 < L_DIM) ? acc1[nt][3] * rn1 : -1e30f;
            mx0 = fmaxf(mx0, fmaxf(acc1[nt][0], acc1[nt][1]));
            mx1 = fmaxf(mx1, fmaxf(acc1[nt][2], acc1[nt][3]));
        }
        mx0 = fmaxf(mx0, __shfl_xor_sync(0xffffffffu, mx0, 1));
        mx0 = fmaxf(mx0, __shfl_xor_sync(0xffffffffu, mx0, 2));
        mx1 = fmaxf(mx1, __shfl_xor_sync(0xffffffffu, mx1, 1));
        mx1 = fmaxf(mx1, __shfl_xor_sync(0xffffffffu, mx1, 2));
        float s0 = 0.f, s1 = 0.f;
        #pragma unroll
        for (int nt = 0; nt < 8; nt++) {
            acc1[nt][0] = __expf(acc1[nt][0] - mx0);
            acc1[nt][1] = __expf(acc1[nt][1] - mx0);
            acc1[nt][2] = __expf(acc1[nt][2] - mx1);
            acc1[nt][3] = __expf(acc1[nt][3] - mx1);
            s0 += acc1[nt][0] + acc1[nt][1];
            s1 += acc1[nt][2] + acc1[nt][3];
        }
        s0 += __shfl_xor_sync(0xffffffffu, s0, 1);
        s0 += __shfl_xor_sync(0xffffffffu, s0, 2);
        s1 += __shfl_xor_sync(0xffffffffu, s1, 1);
        s1 += __shfl_xor_sync(0xffffffffu, s1, 2);
        float inv0 = 1.f / s0, inv1 = 1.f / s1;

        // weights -> GEMM2 A-frags (hi/lo), direct D->A layout mapping
        uint32_t wh[4][4], wl[4][4];
        #pragma unroll
        for (int ks = 0; ks < 4; ks++) {
            int ntA = 2 * ks, ntB = 2 * ks + 1;
            split2(acc1[ntA][0] * inv0, acc1[ntA][1] * inv0, wh[ks][0], wl[ks][0]);
            split2(acc1[ntA][2] * inv1, acc1[ntA][3] * inv1, wh[ks][1], wl[ks][1]);
            split2(acc1[ntB][0] * inv0, acc1[ntB][1] * inv0, wh[ks][2], wl[ks][2]);
            split2(acc1[ntB][2] * inv1, acc1[ntB][3] * inv1, wh[ks][3], wl[ks][3]);
        }

        // ---- GEMM2 in two halves of 8 n-tiles (reg pressure) ----
        #pragma unroll
        for (int half = 0; half < 2; half++) {
            float acc2[8][4];
            #pragma unroll
            for (int nt = 0; nt < 8; nt++)
                #pragma unroll
                for (int i = 0; i < 4; i++) acc2[nt][i] = 0.f;

            #pragma unroll
            for (int nt = 0; nt < 8; nt++) {
                int ntg = half * 8 + nt;
                #pragma unroll
                for (int ks = 0; ks < 4; ks++) {
                    uint4 v = vf4[(ks * 16 + ntg) * 32 + lane];
                    uint32_t bhv[2] = { v.x, v.y };
                    uint32_t blv[2] = { v.z, v.w };
                    mma_bf16(acc2[nt], wh[ks], bhv, acc2[nt]);
                    mma_bf16(acc2[nt], wl[ks], bhv, acc2[nt]);
                    mma_bf16(acc2[nt], wh[ks], blv, acc2[nt]);
                }
            }
            // epilogue: coalesced 32B-sector stores, streaming
            #pragma unroll
            for (int nt = 0; nt < 8; nt++) {
                int c0 = (half * 8 + nt) * 8 + 2 * q;
                size_t base = (size_t)c0 * HW_DIM + n0;
                __stcs(&ob[base + row0],          acc2[nt][0]);
                __stcs(&ob[base + HW_DIM + row0], acc2[nt][1]);
                __stcs(&ob[base + row1],          acc2[nt][2]);
                __stcs(&ob[base + HW_DIM + row1], acc2[nt][3]);
            }
        }
    }
}

// ---------------------------------------------------------------- launcher
extern "C" void kernel_launch(void* const* d_in, const int* in_sizes, int n_in,
                              void* d_out, int out_size) {
    const float* x      = (const float*)d_in[0];
    const float* keys   = (const float*)d_in[1];
    const float* values = (const float*)d_in[2];
    float* out = (float*)d_out;

    cudaFuncSetAttribute(memmod_kernel,
                         cudaFuncAttributeMaxDynamicSharedMemorySize, SMEM_BYTES);

    prep_kernel<<<1, 256>>>(keys, values);
    dim3 grid(HW_DIM / (TILES_PER_CTA * TILE_PX), B_DIM);
    memmod_kernel<<<grid, 256, SMEM_BYTES>>>(x, out);
}

// round 5
// speedup vs baseline: 1.3966x; 1.1227x over previous
#include <cuda_runtime.h>
#include <cuda_bf16.h>
#include <stdint.h>

#define B_DIM 64
#define C_DIM 128
#define HW_DIM 16384
#define L_DIM 50
#define TILES_PER_CTA 8
#define TILE_PX 128
#define CHUNK_CH 16          // channels per staging chunk
#define CHUNKS_PER_TILE 8
#define NBUF 3               // staging buffers (pipeline depth 3)

// shared memory map (u32 units)
#define STAG_OFF32  0                      // 3 bufs x 16ch x 128px = 6144
#define STAG_BUF32  2048
#define XIMG_OFF32  6144                   // bf16x2 image [px][colmap], stride 65
#define XIMG_STRIDE 65                     // 65*128 = 8320
#define KF2_OFF32   14464                  // uint2 kfrags: 4096 u32
#define VF4_OFF32   18560                  // uint4 vfrags: 8192 u32
#define SSQ_OFF32   26752                  // 256 floats
#define SMEM_U32    27008
#define SMEM_BYTES  (SMEM_U32 * 4)         // 108032

static __device__ __align__(16) uint2 g_kfrag2[2048];
static __device__ __align__(16) uint4 g_vfrag4[2048];

// ---------------------------------------------------------------- helpers
__device__ __forceinline__ uint32_t smem_u32(const void* p) {
    uint32_t a;
    asm("{ .reg .u64 t; cvta.to.shared.u64 t, %1; cvt.u32.u64 %0, t; }"
        : "=r"(a) : "l"(p));
    return a;
}
__device__ __forceinline__ void cp_async16(uint32_t dst, const void* src) {
    asm volatile("cp.async.cg.shared.global [%0], [%1], 16;"
                 :: "r"(dst), "l"(src));
}
__device__ __forceinline__ void cp_async_commit() {
    asm volatile("cp.async.commit_group;");
}
__device__ __forceinline__ void cp_async_wait2() {
    asm volatile("cp.async.wait_group 2;");
}
__device__ __forceinline__ uint32_t packbf(float lo, float hi) {
    __nv_bfloat162 t = __floats2bfloat162_rn(lo, hi);
    return *(uint32_t*)&t;
}
__device__ __forceinline__ void split2(float a, float b, uint32_t& hi, uint32_t& lo) {
    __nv_bfloat16 ha = __float2bfloat16(a);
    __nv_bfloat16 hb = __float2bfloat16(b);
    hi = ((uint32_t)__bfloat16_as_ushort(hb) << 16) | (uint32_t)__bfloat16_as_ushort(ha);
    lo = packbf(a - __bfloat162float(ha), b - __bfloat162float(hb));
}
__device__ __forceinline__ void mma_bf16(float* d, const uint32_t* a,
                                         const uint32_t* b, const float* c) {
    asm volatile(
        "mma.sync.aligned.m16n8k16.row.col.f32.bf16.bf16.f32 "
        "{%0,%1,%2,%3}, {%4,%5,%6,%7}, {%8,%9}, {%10,%11,%12,%13};"
        : "=f"(d[0]), "=f"(d[1]), "=f"(d[2]), "=f"(d[3])
        : "r"(a[0]), "r"(a[1]), "r"(a[2]), "r"(a[3]),
          "r"(b[0]), "r"(b[1]),
          "f"(c[0]), "f"(c[1]), "f"(c[2]), "f"(c[3]));
}

// ---------------------------------------------------------------- prep
//   kf2[(ks*8+nt)*32+lane]  = uint2{ b(r=0), b(r=1) }          (GEMM1 B, bf16)
//   vf4[(ks*16+nt)*32+lane] = uint4{ vh(r0), vh(r1), vl(r0), vl(r1) } (GEMM2 B)
__global__ void prep_kernel(const float* __restrict__ keys,
                            const float* __restrict__ values) {
    __shared__ float knorm[64];
    int tid = threadIdx.x;
    if (tid < 64) {
        float s = 0.f;
        if (tid < L_DIM) {
            for (int c = 0; c < C_DIM; c++) {
                float v = keys[tid * C_DIM + c];
                s += v * v;
            }
        }
        knorm[tid] = (tid < L_DIM) ? rsqrtf(fmaxf(s, 1e-24f)) : 0.f;
    }
    __syncthreads();

    for (int idx = tid; idx < 2048; idx += blockDim.x) {
        int lane = idx & 31, f = idx >> 5;
        int nt = f & 7, ks = f >> 3;
        int g = lane >> 2, q = lane & 3;
        int l = nt * 8 + g;
        uint2 o = make_uint2(0u, 0u);
        if (l < L_DIM) {
            float nrm = knorm[l];
            int k0 = ks * 16 + 2 * q;
            o.x = packbf(keys[l * C_DIM + k0]     * nrm,
                         keys[l * C_DIM + k0 + 1] * nrm);
            o.y = packbf(keys[l * C_DIM + k0 + 8]     * nrm,
                         keys[l * C_DIM + k0 + 8 + 1] * nrm);
        }
        g_kfrag2[idx] = o;
    }
    for (int idx = tid; idx < 2048; idx += blockDim.x) {
        int lane = idx & 31, f = idx >> 5;
        int nt = f & 15, ks = f >> 4;
        int g = lane >> 2, q = lane & 3;
        int n = nt * 8 + g;
        int k0 = ks * 16 + 2 * q;
        int k1 = k0 + 8;
        float a0 = (k0     < L_DIM) ? values[k0 * C_DIM + n]       : 0.f;
        float a1 = (k0 + 1 < L_DIM) ? values[(k0 + 1) * C_DIM + n] : 0.f;
        float b0 = (k1     < L_DIM) ? values[k1 * C_DIM + n]       : 0.f;
        float b1 = (k1 + 1 < L_DIM) ? values[(k1 + 1) * C_DIM + n] : 0.f;
        uint4 o;
        split2(a0, a1, o.x, o.z);
        split2(b0, b1, o.y, o.w);
        g_vfrag4[idx] = o;
    }
}

// ---------------------------------------------------------------- main
__global__ void __launch_bounds__(256, 2)
memmod_kernel(const float* __restrict__ x, float* __restrict__ out) {
    extern __shared__ float smem[];
    uint32_t* sm32 = (uint32_t*)smem;
    const uint32_t sbase = smem_u32(smem);

    const int tid  = threadIdx.x;
    const int wid  = tid >> 5;
    const int lane = tid & 31;
    const int g    = lane >> 2;
    const int q    = lane & 3;
    const int b    = blockIdx.y;

    // copy baked fragment images into smem (48 KB)
    {
        const uint4* s1 = (const uint4*)g_kfrag2;
        const uint4* s2 = (const uint4*)g_vfrag4;
        uint4* d1 = (uint4*)(sm32 + KF2_OFF32);
        uint4* d2 = (uint4*)(sm32 + VF4_OFF32);
        #pragma unroll
        for (int i = 0; i < 4; i++) d1[tid + i * 256] = s1[tid + i * 256];
        #pragma unroll
        for (int i = 0; i < 8; i++) d2[tid + i * 256] = s2[tid + i * 256];
    }

    const float* xb = x   + (size_t)b * C_DIM * HW_DIM;
    float*       ob = out + (size_t)b * C_DIM * HW_DIM;

    const int m0   = wid * 16;
    const int row0 = m0 + g;
    const int row1 = m0 + g + 8;
    const int p    = tid & 127;
    const int hh   = tid >> 7;

    const uint2* kf2 = (const uint2*)(sm32 + KF2_OFF32);
    const uint4* vf4 = (const uint4*)(sm32 + VF4_OFF32);
    const uint32_t* xim = sm32 + XIMG_OFF32;

    const int tile0 = blockIdx.x * TILES_PER_CTA;
    const int c_ld  = tid >> 5;          // 0..7: channel sub-index for loads
    const int j4    = (tid & 31) << 2;   // pixel sub-offset for loads

    // issue chunk loads: global chunk id gc = t*8 + c, buffer gc % 3
    auto issue_chunk = [&](int gc) {
        if (gc < TILES_PER_CTA * CHUNKS_PER_TILE) {
            int tt = gc >> 3, cc = gc & 7;
            int nn0 = (tile0 + tt) * TILE_PX;
            uint32_t buf = sbase + (uint32_t)((gc % NBUF) * STAG_BUF32) * 4;
            #pragma unroll
            for (int i = 0; i < 2; i++) {
                int c = c_ld + i * 8;
                cp_async16(buf + (uint32_t)(c * 128 + j4) * 4,
                           xb + (size_t)(cc * CHUNK_CH + c) * HW_DIM + nn0 + j4);
            }
        }
        cp_async_commit();
    };

    // prologue: 3 chunks in flight
    issue_chunk(0);
    issue_chunk(1);
    issue_chunk(2);

    for (int t = 0; t < TILES_PER_CTA; t++) {
        const int n0 = (tile0 + t) * TILE_PX;

        // ---- convert loop: 8 chunks of 16 channels, depth-3 pipeline ----
        float ssq = 0.f;
        for (int c = 0; c < CHUNKS_PER_TILE; c++) {
            const int gc = t * CHUNKS_PER_TILE + c;
            cp_async_wait2();      // chunk gc arrived
            __syncthreads();       // visible to all; also guards ximg reuse at c==0
            const float* buf = smem + (gc % NBUF) * STAG_BUF32;
            #pragma unroll
            for (int jj = 0; jj < 4; jj++) {
                int ccl = hh * 4 + jj;             // pair within chunk 0..7
                int cc  = c * 8 + ccl;             // global pair 0..63
                float v0 = buf[(2 * ccl)     * 128 + p];
                float v1 = buf[(2 * ccl + 1) * 128 + p];
                ssq += v0 * v0 + v1 * v1;
                int colmap = ((cc & 7) << 3) | (cc >> 3);
                sm32[XIMG_OFF32 + p * XIMG_STRIDE + colmap] = packbf(v0, v1);
            }
            __syncthreads();       // all reads of buffer done before refill
            issue_chunk(gc + NBUF);
        }
        smem[SSQ_OFF32 + tid] = ssq;
        __syncthreads();

        // ---- GEMM1: logits[16px x 64slots] per warp, 1-pass bf16 ----
        float acc1[8][4];
        #pragma unroll
        for (int nt = 0; nt < 8; nt++)
            #pragma unroll
            for (int i = 0; i < 4; i++) acc1[nt][i] = 0.f;

        #pragma unroll
        for (int ks = 0; ks < 8; ks++) {
            uint32_t a[4];
            int base0 = row0 * XIMG_STRIDE + 8 * q + ks;
            int base1 = row1 * XIMG_STRIDE + 8 * q + ks;
            a[0] = xim[base0];
            a[1] = xim[base1];
            a[2] = xim[base0 + 32];
            a[3] = xim[base1 + 32];
            #pragma unroll
            for (int nt = 0; nt < 8; nt++) {
                uint2 bb = kf2[(ks * 8 + nt) * 32 + lane];
                mma_bf16(acc1[nt], a, (const uint32_t*)&bb, acc1[nt]);
            }
        }

        // ---- softmax over 64 slots (quad-distributed), fp32 ----
        float rn0 = rsqrtf(fmaxf(smem[SSQ_OFF32 + row0] +
                                 smem[SSQ_OFF32 + row0 + 128], 1e-24f));
        float rn1 = rsqrtf(fmaxf(smem[SSQ_OFF32 + row1] +
                                 smem[SSQ_OFF32 + row1 + 128], 1e-24f));
        float mx0 = -1e30f, mx1 = -1e30f;
        #pragma unroll
        for (int nt = 0; nt < 8; nt++) {
            int l0 = nt * 8 + 2 * q, l1 = l0 + 1;
            acc1[nt][0] = (l0 < L_DIM) ? acc1[nt][0] * rn0 : -1e30f;
            acc1[nt][1] = (l1 < L_DIM) ? acc1[nt][1] * rn0 : -1e30f;
            acc1[nt][2] = (l0 < L_DIM) ? acc1[nt][2] * rn1 : -1e30f;
            acc1[nt][3] = (l1 < L_DIM) ? acc1[nt][3] * rn1 : -1e30f;
            mx0 = fmaxf(mx0, fmaxf(acc1[nt][0], acc1[nt][1]));
            mx1 = fmaxf(mx1, fmaxf(acc1[nt][2], acc1[nt][3]));
        }
        mx0 = fmaxf(mx0, __shfl_xor_sync(0xffffffffu, mx0, 1));
        mx0 = fmaxf(mx0, __shfl_xor_sync(0xffffffffu, mx0, 2));
        mx1 = fmaxf(mx1, __shfl_xor_sync(0xffffffffu, mx1, 1));
        mx1 = fmaxf(mx1, __shfl_xor_sync(0xffffffffu, mx1, 2));
        float s0 = 0.f, s1 = 0.f;
        #pragma unroll
        for (int nt = 0; nt < 8; nt++) {
            acc1[nt][0] = __expf(acc1[nt][0] - mx0);
            acc1[nt][1] = __expf(acc1[nt][1] - mx0);
            acc1[nt][2] = __expf(acc1[nt][2] - mx1);
            acc1[nt][3] = __expf(acc1[nt][3] - mx1);
            s0 += acc1[nt][0] + acc1[nt][1];
            s1 += acc1[nt][2] + acc1[nt][3];
        }
        s0 += __shfl_xor_sync(0xffffffffu, s0, 1);
        s0 += __shfl_xor_sync(0xffffffffu, s0, 2);
        s1 += __shfl_xor_sync(0xffffffffu, s1, 1);
        s1 += __shfl_xor_sync(0xffffffffu, s1, 2);
        float inv0 = 1.f / s0, inv1 = 1.f / s1;

        // weights -> GEMM2 A-frags (hi/lo), direct D->A layout mapping
        uint32_t wh[4][4], wl[4][4];
        #pragma unroll
        for (int ks = 0; ks < 4; ks++) {
            int ntA = 2 * ks, ntB = 2 * ks + 1;
            split2(acc1[ntA][0] * inv0, acc1[ntA][1] * inv0, wh[ks][0], wl[ks][0]);
            split2(acc1[ntA][2] * inv1, acc1[ntA][3] * inv1, wh[ks][1], wl[ks][1]);
            split2(acc1[ntB][0] * inv0, acc1[ntB][1] * inv0, wh[ks][2], wl[ks][2]);
            split2(acc1[ntB][2] * inv1, acc1[ntB][3] * inv1, wh[ks][3], wl[ks][3]);
        }

        // ---- GEMM2 in two halves of 8 n-tiles (reg pressure) ----
        #pragma unroll
        for (int half = 0; half < 2; half++) {
            float acc2[8][4];
            #pragma unroll
            for (int nt = 0; nt < 8; nt++)
                #pragma unroll
                for (int i = 0; i < 4; i++) acc2[nt][i] = 0.f;

            #pragma unroll
            for (int nt = 0; nt < 8; nt++) {
                int ntg = half * 8 + nt;
                #pragma unroll
                for (int ks = 0; ks < 4; ks++) {
                    uint4 v = vf4[(ks * 16 + ntg) * 32 + lane];
                    uint32_t bhv[2] = { v.x, v.y };
                    uint32_t blv[2] = { v.z, v.w };
                    mma_bf16(acc2[nt], wh[ks], bhv, acc2[nt]);
                    mma_bf16(acc2[nt], wl[ks], bhv, acc2[nt]);
                    mma_bf16(acc2[nt], wh[ks], blv, acc2[nt]);
                }
            }
            #pragma unroll
            for (int nt = 0; nt < 8; nt++) {
                int c0 = (half * 8 + nt) * 8 + 2 * q;
                size_t base = (size_t)c0 * HW_DIM + n0;
                __stcs(&ob[base + row0],          acc2[nt][0]);
                __stcs(&ob[base + HW_DIM + row0], acc2[nt][1]);
                __stcs(&ob[base + row1],          acc2[nt][2]);
                __stcs(&ob[base + HW_DIM + row1], acc2[nt][3]);
            }
        }
    }
}

// ---------------------------------------------------------------- launcher
extern "C" void kernel_launch(void* const* d_in, const int* in_sizes, int n_in,
                              void* d_out, int out_size) {
    const float* x      = (const float*)d_in[0];
    const float* keys   = (const float*)d_in[1];
    const float* values = (const float*)d_in[2];
    float* out = (float*)d_out;

    cudaFuncSetAttribute(memmod_kernel,
                         cudaFuncAttributeMaxDynamicSharedMemorySize, SMEM_BYTES);

    prep_kernel<<<1, 256>>>(keys, values);
    dim3 grid(HW_DIM / (TILES_PER_CTA * TILE_PX), B_DIM);
    memmod_kernel<<<grid, 256, SMEM_BYTES>>>(x, out);
}